// round 1
// baseline (speedup 1.0000x reference)
#include <cuda_runtime.h>

// Problem dims (fixed by the reference)
#define BB 16
#define NN 2048
#define EE 256
#define KCH 8   // precompute K-split blocks

// Scratch (allocation-free rule: __device__ globals)
__device__ float2 g_probes[BB * NN];          // compacted probe coords per batch
__device__ int    g_pcount[BB];               // probe counts
__device__ float  g_part[KCH][4][EE];         // partial folded coefficients
__device__ float  g_coef[4][EE];              // A0, A1, C, D

// ---------------------------------------------------------------------------
// Kernel 1: grid = BB + KCH blocks.
//   blocks [0, BB):  detect probe dtype layout + compact probe coords
//   blocks [BB, BB+KCH): partial folded-coefficient compute (K-split of W_out)
// ---------------------------------------------------------------------------
__global__ __launch_bounds__(256) void prep_kernel(
    const float*    __restrict__ locs,
    const unsigned* __restrict__ probe_raw,
    const float*    __restrict__ W_node,
    const float*    __restrict__ b_node,
    const float*    __restrict__ W_dist,
    const float*    __restrict__ b_dist,
    const float*    __restrict__ W_out)
{
    int blk = blockIdx.x;
    if (blk < BB) {
        // ---- layout detection over first (BB*NN)/4 words = 32KB,
        //      valid to read in both candidate layouts ----
        bool bad = false;
        for (int i = threadIdx.x; i < (BB * NN) / 4; i += 256) {
            unsigned v = probe_raw[i];
            // int32 bool -> {0,1}; float32 bool -> {0, 0x3F800000}
            if (v != 0u && v != 1u && v != 0x3F800000u) bad = true;
        }
        int is8 = __syncthreads_or((int)bad);   // else: 4-byte-per-element

        __shared__ int s_cnt;
        if (threadIdx.x == 0) s_cnt = 0;
        __syncthreads();

        const float2* lp = (const float2*)locs + blk * NN;
        if (is8) {
            const unsigned char* p8 = (const unsigned char*)probe_raw;
            for (int n = threadIdx.x; n < NN; n += 256) {
                if (p8[blk * NN + n] != 0) {
                    int slot = atomicAdd(&s_cnt, 1);
                    g_probes[blk * NN + slot] = lp[n];
                }
            }
        } else {
            for (int n = threadIdx.x; n < NN; n += 256) {
                if (probe_raw[blk * NN + n] != 0u) {
                    int slot = atomicAdd(&s_cnt, 1);
                    g_probes[blk * NN + slot] = lp[n];
                }
            }
        }
        __syncthreads();
        if (threadIdx.x == 0) g_pcount[blk] = s_cnt;
    } else {
        // ---- folded coefficients, K-chunk c ----
        int c = blk - BB;
        int e = threadIdx.x;
        float a0 = 0.f, a1 = 0.f, cc = 0.f, dd = 0.f;
        int k0 = c * (EE / KCH);
#pragma unroll 4
        for (int kk = 0; kk < EE / KCH; kk++) {
            int k = k0 + kk;
            float wt = W_out[k * EE + e];          // top half row k
            float wb = W_out[(EE + k) * EE + e];   // bottom half row k
            a0 = fmaf(W_node[k],      wt, a0);
            a1 = fmaf(W_node[EE + k], wt, a1);
            cc = fmaf(W_dist[k],      wb, cc);
            dd = fmaf(b_node[k], wt, dd);
            dd = fmaf(b_dist[k], wb, dd);
        }
        g_part[c][0][e] = a0;
        g_part[c][1][e] = a1;
        g_part[c][2][e] = cc;
        g_part[c][3][e] = dd;
    }
}

// ---------------------------------------------------------------------------
// Kernel 2: reduce partial coefficients (deterministic fixed-order sum)
// ---------------------------------------------------------------------------
__global__ __launch_bounds__(EE) void reduce_kernel(const float* __restrict__ b_out)
{
    int e = threadIdx.x;
    float s0 = 0.f, s1 = 0.f, s2 = 0.f, s3 = 0.f;
#pragma unroll
    for (int c = 0; c < KCH; c++) {
        s0 += g_part[c][0][e];
        s1 += g_part[c][1][e];
        s2 += g_part[c][2][e];
        s3 += g_part[c][3][e];
    }
    g_coef[0][e] = s0;
    g_coef[1][e] = s1;
    g_coef[2][e] = s2;
    g_coef[3][e] = s3 + b_out[e];
}

// ---------------------------------------------------------------------------
// Kernel 3: fused min-dist + affine epilogue.
// grid = BB * (NN/256) = 128 blocks, 256 threads.
// Each block: one batch b, one tile of 256 n values.
//   Phase 1: each thread computes min over probes of  |p|^2 - 2 x·p
//            (same cancellation structure as the reference's cdist)
//   Phase 2: cooperative coalesced float4 write of the 256x256 output tile.
// ---------------------------------------------------------------------------
__global__ __launch_bounds__(256) void main_kernel(
    const float* __restrict__ locs, float* __restrict__ out)
{
    __shared__ float4 sp[NN];            // (px, py, |p|^2, pad)  32KB
    __shared__ float  sx[256], sy[256], smd[256];

    int b     = blockIdx.x >> 3;
    int nbase = (blockIdx.x & 7) << 8;
    int tid   = threadIdx.x;
    int P     = g_pcount[b];

    for (int i = tid; i < P; i += 256) {
        float2 p = g_probes[b * NN + i];
        sp[i] = make_float4(p.x, p.y, fmaf(p.x, p.x, p.y * p.y), 0.f);
    }
    float2 me = ((const float2*)locs)[b * NN + nbase + tid];
    __syncthreads();

    float x = me.x, y = me.y;
    float tx = -2.f * x, ty = -2.f * y;
    float m0 = 3.4e38f, m1 = 3.4e38f, m2 = 3.4e38f, m3 = 3.4e38f;

    int i = 0;
    for (; i + 4 <= P; i += 4) {
        float4 p0 = sp[i], p1 = sp[i + 1], p2 = sp[i + 2], p3 = sp[i + 3];
        m0 = fminf(m0, fmaf(tx, p0.x, fmaf(ty, p0.y, p0.z)));
        m1 = fminf(m1, fmaf(tx, p1.x, fmaf(ty, p1.y, p1.z)));
        m2 = fminf(m2, fmaf(tx, p2.x, fmaf(ty, p2.y, p2.z)));
        m3 = fminf(m3, fmaf(tx, p3.x, fmaf(ty, p3.y, p3.z)));
    }
    for (; i < P; i++) {
        float4 p0 = sp[i];
        m0 = fminf(m0, fmaf(tx, p0.x, fmaf(ty, p0.y, p0.z)));
    }
    float ms = fminf(fminf(m0, m1), fminf(m2, m3));
    float d2 = fmaxf(fmaf(x, x, y * y) + ms, 0.f);   // safe clamp, like reference
    float md = sqrtf(d2);

    sx[tid] = x; sy[tid] = y; smd[tid] = md;

    // Preload this thread's slice of the folded coefficients (e0..e0+3)
    int e0 = (tid & 63) << 2;
    float4 A0 = *(const float4*)&g_coef[0][e0];
    float4 A1 = *(const float4*)&g_coef[1][e0];
    float4 C  = *(const float4*)&g_coef[2][e0];
    float4 Dv = *(const float4*)&g_coef[3][e0];
    __syncthreads();

    // 4 rows per iteration; each warp handles one row (broadcast shared reads),
    // contiguous 128B-per-8-threads STG.128 writes.
    int rsub    = tid >> 6;
    int rowbase = b * NN + nbase;
#pragma unroll 4
    for (int r0 = 0; r0 < 256; r0 += 4) {
        int r = r0 + rsub;
        float xx = sx[r], yy = sy[r], mm = smd[r];
        float4 v;
        v.x = fmaf(xx, A0.x, fmaf(yy, A1.x, fmaf(mm, C.x, Dv.x)));
        v.y = fmaf(xx, A0.y, fmaf(yy, A1.y, fmaf(mm, C.y, Dv.y)));
        v.z = fmaf(xx, A0.z, fmaf(yy, A1.z, fmaf(mm, C.z, Dv.z)));
        v.w = fmaf(xx, A0.w, fmaf(yy, A1.w, fmaf(mm, C.w, Dv.w)));
        *(float4*)(out + (size_t)(rowbase + r) * EE + e0) = v;
    }
}

// ---------------------------------------------------------------------------
extern "C" void kernel_launch(void* const* d_in, const int* in_sizes, int n_in,
                              void* d_out, int out_size)
{
    const float*    locs   = (const float*)d_in[0];
    const unsigned* probe  = (const unsigned*)d_in[1];
    const float*    W_node = (const float*)d_in[2];
    const float*    b_node = (const float*)d_in[3];
    const float*    W_dist = (const float*)d_in[4];
    const float*    b_dist = (const float*)d_in[5];
    const float*    W_out  = (const float*)d_in[6];
    const float*    b_out  = (const float*)d_in[7];
    float* out = (float*)d_out;

    prep_kernel<<<BB + KCH, 256>>>(locs, probe, W_node, b_node, W_dist, b_dist, W_out);
    reduce_kernel<<<1, EE>>>(b_out);
    main_kernel<<<BB * (NN / 256), 256>>>(locs, out);
}

// round 2
// speedup vs baseline: 1.1864x; 1.1864x over previous
#include <cuda_runtime.h>

#define BB 16
#define NN 2048
#define EE 256
#define KCH 8

typedef unsigned long long ull;

// Scratch (allocation-free rule: __device__ globals)
// Probe pair-SoA per batch: xy pairs (x0,x1,y0,y1) and z pairs (z0,z1)
__device__ float g_pxy[BB * NN * 2];          // [b][pair][4] = 512KB
__device__ ull   g_pzz[BB * NN / 2];          // [b][pair]    = 128KB
__device__ int   g_pcount[BB];                // padded counts (multiple of 8)
__device__ float g_part[KCH][4][EE];          // partial folded coefficients

// ---- f32x2 helpers (sm_103a packed fp32 pipe) ------------------------------
__device__ __forceinline__ ull fma2(ull a, ull b, ull c) {
    ull d;
    asm("fma.rn.f32x2 %0, %1, %2, %3;" : "=l"(d) : "l"(a), "l"(b), "l"(c));
    return d;
}
__device__ __forceinline__ ull pack2(float lo, float hi) {
    ull d;
    asm("mov.b64 %0, {%1, %2};" : "=l"(d) : "f"(lo), "f"(hi));
    return d;
}
__device__ __forceinline__ float lo2(ull v) {
    float f; asm("{ .reg .f32 hi; mov.b64 {%0, hi}, %1; }" : "=f"(f) : "l"(v));
    return f;
}
__device__ __forceinline__ float hi2(ull v) {
    float f; asm("{ .reg .f32 lo; mov.b64 {lo, %0}, %1; }" : "=f"(f) : "l"(v));
    return f;
}

// ---------------------------------------------------------------------------
// Kernel 1: grid = BB + KCH blocks, 256 threads.
//   blocks [0, BB):      probe dtype detect (512-word slice) + compact to
//                        pair-SoA, pad to multiple of 8 with z=3.2e38
//   blocks [BB, BB+KCH): K-split partial folded coefficients
// ---------------------------------------------------------------------------
__global__ __launch_bounds__(256) void prep_kernel(
    const float*    __restrict__ locs,
    const unsigned* __restrict__ probe_raw,
    const float*    __restrict__ W_node,
    const float*    __restrict__ b_node,
    const float*    __restrict__ W_dist,
    const float*    __restrict__ b_dist,
    const float*    __restrict__ W_out)
{
    int blk = blockIdx.x;
    int tid = threadIdx.x;
    if (blk < BB) {
        // ---- layout detection on this batch's 512-word slice (valid reads
        //      under both candidate layouts) ----
        bool bad = false;
        #pragma unroll
        for (int j = 0; j < 2; j++) {
            unsigned v = probe_raw[blk * 512 + j * 256 + tid];
            if (v != 0u && v != 1u && v != 0x3F800000u) bad = true;
        }
        int is8 = __syncthreads_or((int)bad);   // bad word => 1-byte bools

        __shared__ int s_cnt;
        if (tid == 0) s_cnt = 0;
        __syncthreads();

        const float2* lp  = (const float2*)locs + blk * NN;
        float*        pxy = g_pxy + blk * NN * 2;
        float*        pzz = (float*)(g_pzz + blk * (NN / 2));

        if (is8) {
            const unsigned char* p8 = (const unsigned char*)probe_raw + blk * NN;
            for (int n = tid; n < NN; n += 256) {
                if (p8[n] != 0) {
                    int s = atomicAdd(&s_cnt, 1);
                    float2 p = lp[n];
                    int pr = s >> 1, c = s & 1;
                    pxy[pr * 4 + c]     = p.x;
                    pxy[pr * 4 + 2 + c] = p.y;
                    pzz[s]              = fmaf(p.x, p.x, p.y * p.y);
                }
            }
        } else {
            const unsigned* p32 = probe_raw + blk * NN;
            for (int n = tid; n < NN; n += 256) {
                if (p32[n] != 0u) {
                    int s = atomicAdd(&s_cnt, 1);
                    float2 p = lp[n];
                    int pr = s >> 1, c = s & 1;
                    pxy[pr * 4 + c]     = p.x;
                    pxy[pr * 4 + 2 + c] = p.y;
                    pzz[s]              = fmaf(p.x, p.x, p.y * p.y);
                }
            }
        }
        __syncthreads();
        int P    = s_cnt;
        int Ppad = (P + 7) & ~7;
        for (int s = P + tid; s < Ppad; s += 256) {   // sentinel pads
            int pr = s >> 1, c = s & 1;
            pxy[pr * 4 + c]     = 0.f;
            pxy[pr * 4 + 2 + c] = 0.f;
            pzz[s]              = 3.2e38f;
        }
        if (tid == 0) g_pcount[blk] = Ppad;
    } else {
        // ---- folded coefficients, K-chunk c (same summation order as R1) ----
        int c = blk - BB;
        int e = tid;
        float a0 = 0.f, a1 = 0.f, cc = 0.f, dd = 0.f;
        int k0 = c * (EE / KCH);
        #pragma unroll 8
        for (int kk = 0; kk < EE / KCH; kk++) {
            int k = k0 + kk;
            float wt = W_out[k * EE + e];
            float wb = W_out[(EE + k) * EE + e];
            a0 = fmaf(W_node[k],      wt, a0);
            a1 = fmaf(W_node[EE + k], wt, a1);
            cc = fmaf(W_dist[k],      wb, cc);
            dd = fmaf(b_node[k], wt, dd);
            dd = fmaf(b_dist[k], wb, dd);
        }
        g_part[c][0][e] = a0;
        g_part[c][1][e] = a1;
        g_part[c][2][e] = cc;
        g_part[c][3][e] = dd;
    }
}

// ---------------------------------------------------------------------------
// Kernel 2: fused coef-reduce + min-dist (f32x2 packed) + affine epilogue.
// grid = BB*8 = 128 blocks, 256 threads; block = (batch b, 256-node tile).
// ---------------------------------------------------------------------------
__global__ __launch_bounds__(256) void main_kernel(
    const float* __restrict__ locs,
    const float* __restrict__ b_out,
    float*       __restrict__ out)
{
    __shared__ float4 s_xy[NN / 2];      // (x0,x1,y0,y1) per probe pair, 16KB
    __shared__ ull    s_zz[NN / 2];      // (z0,z1) per pair, 8KB
    __shared__ float4 s_row[256];        // (x, y, min_dist, -) per node, 4KB
    __shared__ float  s_coef[4][EE];     // folded A0,A1,C,D, 4KB

    int b     = blockIdx.x >> 3;
    int nbase = (blockIdx.x & 7) << 8;
    int tid   = threadIdx.x;

    // ---- redundant per-block coefficient reduce (fixed order) ----
    {
        float c0 = 0.f, c1 = 0.f, c2 = 0.f, c3 = 0.f;
        #pragma unroll
        for (int c = 0; c < KCH; c++) {
            c0 += g_part[c][0][tid];
            c1 += g_part[c][1][tid];
            c2 += g_part[c][2][tid];
            c3 += g_part[c][3][tid];
        }
        s_coef[0][tid] = c0;
        s_coef[1][tid] = c1;
        s_coef[2][tid] = c2;
        s_coef[3][tid] = c3 + b_out[tid];
    }

    // ---- stage probe pairs into shared ----
    int np = g_pcount[b] >> 1;           // pairs, multiple of 4
    {
        const float4* gxy = (const float4*)(g_pxy + b * NN * 2);
        const ull*    gzz = g_pzz + b * (NN / 2);
        for (int i = tid; i < np; i += 256) {
            s_xy[i] = gxy[i];
            s_zz[i] = gzz[i];
        }
    }
    float2 me = ((const float2*)locs)[b * NN + nbase + tid];
    __syncthreads();

    // ---- packed min loop:  score = z - 2x*px - 2y*py,  2 probes / FFMA2 pair ----
    float ntx = -2.f * me.x, nty = -2.f * me.y;
    ull tx2 = pack2(ntx, ntx);
    ull ty2 = pack2(nty, nty);
    float m0 = 3.4e38f, m1 = 3.4e38f, m2 = 3.4e38f, m3 = 3.4e38f;
    float m4 = 3.4e38f, m5 = 3.4e38f, m6 = 3.4e38f, m7 = 3.4e38f;

    for (int i = 0; i < np; i += 4) {
        float4 xy0 = s_xy[i],     xy1 = s_xy[i + 1];
        float4 xy2 = s_xy[i + 2], xy3 = s_xy[i + 3];
        ull z0 = s_zz[i], z1 = s_zz[i + 1], z2 = s_zz[i + 2], z3 = s_zz[i + 3];

        ull v0 = fma2(ty2, pack2(xy0.z, xy0.w), fma2(tx2, pack2(xy0.x, xy0.y), z0));
        ull v1 = fma2(ty2, pack2(xy1.z, xy1.w), fma2(tx2, pack2(xy1.x, xy1.y), z1));
        ull v2 = fma2(ty2, pack2(xy2.z, xy2.w), fma2(tx2, pack2(xy2.x, xy2.y), z2));
        ull v3 = fma2(ty2, pack2(xy3.z, xy3.w), fma2(tx2, pack2(xy3.x, xy3.y), z3));

        m0 = fminf(m0, lo2(v0));  m1 = fminf(m1, hi2(v0));
        m2 = fminf(m2, lo2(v1));  m3 = fminf(m3, hi2(v1));
        m4 = fminf(m4, lo2(v2));  m5 = fminf(m5, hi2(v2));
        m6 = fminf(m6, lo2(v3));  m7 = fminf(m7, hi2(v3));
    }
    float ms = fminf(fminf(fminf(m0, m1), fminf(m2, m3)),
                     fminf(fminf(m4, m5), fminf(m6, m7)));
    float d2 = fmaxf(fmaf(me.x, me.x, me.y * me.y) + ms, 0.f);
    s_row[tid] = make_float4(me.x, me.y, sqrtf(d2), 0.f);
    __syncthreads();

    // ---- epilogue: 4 rows / iter, 2 warps per row, coalesced STG.128 ----
    int e0   = (tid & 63) << 2;
    int rsub = tid >> 6;
    float4 A0 = *(const float4*)&s_coef[0][e0];
    float4 A1 = *(const float4*)&s_coef[1][e0];
    float4 C  = *(const float4*)&s_coef[2][e0];
    float4 Dv = *(const float4*)&s_coef[3][e0];

    int rowbase = b * NN + nbase;
    #pragma unroll 4
    for (int r0 = 0; r0 < 256; r0 += 4) {
        int r = r0 + rsub;
        float4 rw = s_row[r];
        float4 v;
        v.x = fmaf(rw.x, A0.x, fmaf(rw.y, A1.x, fmaf(rw.z, C.x, Dv.x)));
        v.y = fmaf(rw.x, A0.y, fmaf(rw.y, A1.y, fmaf(rw.z, C.y, Dv.y)));
        v.z = fmaf(rw.x, A0.z, fmaf(rw.y, A1.z, fmaf(rw.z, C.z, Dv.z)));
        v.w = fmaf(rw.x, A0.w, fmaf(rw.y, A1.w, fmaf(rw.z, C.w, Dv.w)));
        *(float4*)(out + (size_t)(rowbase + r) * EE + e0) = v;
    }
}

// ---------------------------------------------------------------------------
extern "C" void kernel_launch(void* const* d_in, const int* in_sizes, int n_in,
                              void* d_out, int out_size)
{
    const float*    locs   = (const float*)d_in[0];
    const unsigned* probe  = (const unsigned*)d_in[1];
    const float*    W_node = (const float*)d_in[2];
    const float*    b_node = (const float*)d_in[3];
    const float*    W_dist = (const float*)d_in[4];
    const float*    b_dist = (const float*)d_in[5];
    const float*    W_out  = (const float*)d_in[6];
    const float*    b_out  = (const float*)d_in[7];
    float* out = (float*)d_out;

    prep_kernel<<<BB + KCH, 256>>>(locs, probe, W_node, b_node, W_dist, b_dist, W_out);
    main_kernel<<<BB * (NN / 256), 256>>>(locs, b_out, out);
}

// round 3
// speedup vs baseline: 1.3023x; 1.0977x over previous
#include <cuda_runtime.h>

#define BB 16
#define NN 2048
#define EE 256
#define KCH 8

typedef unsigned long long ull;

// Scratch (__device__ globals; allocation-free rule)
__device__ ulonglong2 g_xy[BB * 1024];        // per probe-pair: xx=(x0,x1), yy=(y0,y1)  256KB
__device__ ull        g_pz[BB * 1024];        // per probe-pair: (z0,z1)                 128KB
__device__ int        g_npq[BB];              // pairs per probe-quarter (multiple of 8)
__device__ float      g_part[KCH][4][EE];     // partial folded coefficients
__device__ float      g_minpart[4][BB * NN];  // per-quarter partial min scores          512KB

// ---- f32x2 helpers ---------------------------------------------------------
__device__ __forceinline__ ull fma2(ull a, ull b, ull c) {
    ull d;
    asm("fma.rn.f32x2 %0, %1, %2, %3;" : "=l"(d) : "l"(a), "l"(b), "l"(c));
    return d;
}
union F2U { ull u; float2 f; };
__device__ __forceinline__ ull pack2(float lo, float hi) {
    F2U t; t.f = make_float2(lo, hi); return t.u;
}
__device__ __forceinline__ void mina(float2& m, ull v) {
    F2U t; t.u = v;
    m.x = fminf(m.x, t.f.x);
    m.y = fminf(m.y, t.f.y);
}

// ---------------------------------------------------------------------------
// Kernel 1: grid = BB + KCH.
//   blocks [0,BB):  probe dtype detect + ballot-compaction into pair-SoA,
//                   padded to 64 probes (32 pairs) with z=3.2e38 sentinels
//   blocks [BB, ..): K-split partial folded coefficients
// ---------------------------------------------------------------------------
__global__ __launch_bounds__(256) void prep_kernel(
    const float*    __restrict__ locs,
    const unsigned* __restrict__ probe_raw,
    const float*    __restrict__ W_node,
    const float*    __restrict__ b_node,
    const float*    __restrict__ W_dist,
    const float*    __restrict__ b_dist,
    const float*    __restrict__ W_out)
{
    int blk = blockIdx.x;
    int tid = threadIdx.x;
    if (blk < BB) {
        // dtype detect on 512 words (valid reads under both layouts)
        bool bad = false;
        #pragma unroll
        for (int j = 0; j < 2; j++) {
            unsigned v = probe_raw[blk * 512 + j * 256 + tid];
            if (v != 0u && v != 1u && v != 0x3F800000u) bad = true;
        }
        int is8 = __syncthreads_or((int)bad);

        __shared__ int s_cnt;
        if (tid == 0) s_cnt = 0;
        __syncthreads();

        const float2* lp = (const float2*)locs + blk * NN;
        unsigned hit[8];
        float2   pl[8];
        if (is8) {
            const unsigned char* p8 = (const unsigned char*)probe_raw + blk * NN;
            #pragma unroll
            for (int j = 0; j < 8; j++) hit[j] = p8[tid + j * 256];
        } else {
            const unsigned* p32 = probe_raw + blk * NN;
            #pragma unroll
            for (int j = 0; j < 8; j++) hit[j] = p32[tid + j * 256];
        }
        #pragma unroll
        for (int j = 0; j < 8; j++) pl[j] = lp[tid + j * 256];

        unsigned lmask = (1u << (tid & 31)) - 1u;
        #pragma unroll
        for (int j = 0; j < 8; j++) {
            bool h = hit[j] != 0u;
            unsigned bal = __ballot_sync(0xFFFFFFFFu, h);
            int base = 0;
            if ((tid & 31) == 0) base = atomicAdd(&s_cnt, __popc(bal));
            base = __shfl_sync(0xFFFFFFFFu, base, 0);
            if (h) {
                int s2 = base + __popc(bal & lmask);
                int pr = s2 >> 1, c = s2 & 1;
                float* fx = (float*)(g_xy + blk * 1024 + pr);
                fx[c]     = pl[j].x;
                fx[2 + c] = pl[j].y;
                ((float*)(g_pz + blk * 1024 + pr))[c] =
                    fmaf(pl[j].x, pl[j].x, pl[j].y * pl[j].y);
            }
        }
        __syncthreads();
        int P    = s_cnt;
        int Ppad = (P + 63) & ~63;              // probes, multiple of 64
        for (int q = P + tid; q < Ppad; q += 256) {
            int pr = q >> 1, c = q & 1;
            float* fx = (float*)(g_xy + blk * 1024 + pr);
            fx[c] = 0.f; fx[2 + c] = 0.f;
            ((float*)(g_pz + blk * 1024 + pr))[c] = 3.2e38f;
        }
        if (tid == 0) g_npq[blk] = Ppad >> 3;   // pairs per quarter
    } else {
        int c = blk - BB;
        int e = tid;
        float a0 = 0.f, a1 = 0.f, cc = 0.f, dd = 0.f;
        int k0 = c * (EE / KCH);
        #pragma unroll 8
        for (int kk = 0; kk < EE / KCH; kk++) {
            int k = k0 + kk;
            float wt = W_out[k * EE + e];
            float wb = W_out[(EE + k) * EE + e];
            a0 = fmaf(W_node[k],      wt, a0);
            a1 = fmaf(W_node[EE + k], wt, a1);
            cc = fmaf(W_dist[k],      wb, cc);
            dd = fmaf(b_node[k], wt, dd);
            dd = fmaf(b_dist[k], wb, dd);
        }
        g_part[c][0][e] = a0;
        g_part[c][1][e] = a1;
        g_part[c][2][e] = cc;
        g_part[c][3][e] = dd;
    }
}

// ---------------------------------------------------------------------------
// Kernel 2: partial min scores. grid = 32 node-tiles x 4 probe-quarters = 128.
// Each thread: 4 nodes (G=4), packed probe-pairs. One probe-pair LDS feeds
// 4 nodes of FFMA2 -> 4x fewer shared-memory instructions than R2.
// ---------------------------------------------------------------------------
__global__ __launch_bounds__(256) void min_kernel(const float* __restrict__ locs)
{
    __shared__ ulonglong2 s_xy[256];   // (xx, yy) per pair
    __shared__ ull        s_zz[256];   // (z0, z1) per pair

    int blk   = blockIdx.x;
    int tile  = blk >> 2;              // 0..31 (1024-node tiles)
    int s     = blk & 3;               // probe quarter
    int b     = tile >> 1;
    int nbase = (tile & 1) << 10;
    int tid   = threadIdx.x;

    int npq = g_npq[b];                // pairs in this quarter (<=256, mult of 8)
    {
        const ulonglong2* gxy = g_xy + b * 1024 + s * npq;
        const ull*        gz  = g_pz + b * 1024 + s * npq;
        if (tid < npq) { s_xy[tid] = gxy[tid]; s_zz[tid] = gz[tid]; }
    }

    float2 me[4];
    ull tx2[4], ty2[4];
    float2 m[4];
    #pragma unroll
    for (int g = 0; g < 4; g++) {
        me[g] = ((const float2*)locs)[b * NN + nbase + tid + (g << 8)];
        float ntx = -2.f * me[g].x, nty = -2.f * me[g].y;
        tx2[g] = pack2(ntx, ntx);
        ty2[g] = pack2(nty, nty);
        m[g]   = make_float2(3.4e38f, 3.4e38f);
    }
    __syncthreads();

    for (int i = 0; i < npq; i += 4) {
        ulonglong2 a0 = s_xy[i],     a1 = s_xy[i + 1];
        ulonglong2 a2 = s_xy[i + 2], a3 = s_xy[i + 3];
        ull z0 = s_zz[i], z1 = s_zz[i + 1], z2 = s_zz[i + 2], z3 = s_zz[i + 3];
        #pragma unroll
        for (int g = 0; g < 4; g++) {
            mina(m[g], fma2(ty2[g], a0.y, fma2(tx2[g], a0.x, z0)));
            mina(m[g], fma2(ty2[g], a1.y, fma2(tx2[g], a1.x, z1)));
            mina(m[g], fma2(ty2[g], a2.y, fma2(tx2[g], a2.x, z2)));
            mina(m[g], fma2(ty2[g], a3.y, fma2(tx2[g], a3.x, z3)));
        }
    }
    #pragma unroll
    for (int g = 0; g < 4; g++)
        g_minpart[s][b * NN + nbase + tid + (g << 8)] = fminf(m[g].x, m[g].y);
}

// ---------------------------------------------------------------------------
// Kernel 3: coef reduce + final min + sqrt + affine tile write.
// grid = BB*8 = 128 blocks of 256 threads; block = (batch, 256-node tile).
// ---------------------------------------------------------------------------
__global__ __launch_bounds__(256) void epi_kernel(
    const float* __restrict__ locs,
    const float* __restrict__ b_out,
    float*       __restrict__ out)
{
    __shared__ float4 s_row[256];
    __shared__ float  s_coef[4][EE];

    int b     = blockIdx.x >> 3;
    int nbase = (blockIdx.x & 7) << 8;
    int tid   = threadIdx.x;

    {   // folded coefficients, fixed-order reduce
        float c0 = 0.f, c1 = 0.f, c2 = 0.f, c3 = 0.f;
        #pragma unroll
        for (int c = 0; c < KCH; c++) {
            c0 += g_part[c][0][tid];
            c1 += g_part[c][1][tid];
            c2 += g_part[c][2][tid];
            c3 += g_part[c][3][tid];
        }
        s_coef[0][tid] = c0;
        s_coef[1][tid] = c1;
        s_coef[2][tid] = c2;
        s_coef[3][tid] = c3 + b_out[tid];
    }

    int node  = b * NN + nbase + tid;
    float2 me = ((const float2*)locs)[node];
    float p0 = g_minpart[0][node], p1 = g_minpart[1][node];
    float p2 = g_minpart[2][node], p3 = g_minpart[3][node];
    float ms = fminf(fminf(p0, p1), fminf(p2, p3));
    float d2 = fmaxf(fmaf(me.x, me.x, me.y * me.y) + ms, 0.f);
    s_row[tid] = make_float4(me.x, me.y, sqrtf(d2), 0.f);
    __syncthreads();

    int e0   = (tid & 63) << 2;
    int rsub = tid >> 6;
    float4 A0 = *(const float4*)&s_coef[0][e0];
    float4 A1 = *(const float4*)&s_coef[1][e0];
    float4 C  = *(const float4*)&s_coef[2][e0];
    float4 Dv = *(const float4*)&s_coef[3][e0];

    int rowbase = b * NN + nbase;
    #pragma unroll 4
    for (int r0 = 0; r0 < 256; r0 += 4) {
        int r = r0 + rsub;
        float4 rw = s_row[r];
        float4 v;
        v.x = fmaf(rw.x, A0.x, fmaf(rw.y, A1.x, fmaf(rw.z, C.x, Dv.x)));
        v.y = fmaf(rw.x, A0.y, fmaf(rw.y, A1.y, fmaf(rw.z, C.y, Dv.y)));
        v.z = fmaf(rw.x, A0.z, fmaf(rw.y, A1.z, fmaf(rw.z, C.z, Dv.z)));
        v.w = fmaf(rw.x, A0.w, fmaf(rw.y, A1.w, fmaf(rw.z, C.w, Dv.w)));
        *(float4*)(out + (size_t)(rowbase + r) * EE + e0) = v;
    }
}

// ---------------------------------------------------------------------------
extern "C" void kernel_launch(void* const* d_in, const int* in_sizes, int n_in,
                              void* d_out, int out_size)
{
    const float*    locs   = (const float*)d_in[0];
    const unsigned* probe  = (const unsigned*)d_in[1];
    const float*    W_node = (const float*)d_in[2];
    const float*    b_node = (const float*)d_in[3];
    const float*    W_dist = (const float*)d_in[4];
    const float*    b_dist = (const float*)d_in[5];
    const float*    W_out  = (const float*)d_in[6];
    const float*    b_out  = (const float*)d_in[7];
    float* out = (float*)d_out;

    prep_kernel<<<BB + KCH, 256>>>(locs, probe, W_node, b_node, W_dist, b_dist, W_out);
    min_kernel<<<128, 256>>>(locs);
    epi_kernel<<<128, 256>>>(locs, b_out, out);
}

// round 4
// speedup vs baseline: 1.4433x; 1.1083x over previous
#include <cuda_runtime.h>

#define BB 16
#define NN 2048
#define EE 256
#define KCH 8

typedef unsigned long long ull;

// Scratch (__device__ globals; allocation-free rule)
__device__ float g_part[KCH][4][EE];     // partial folded coefficients
__device__ float g_minpart[4][BB * NN];  // per-quarter partial min scores (512KB)

// ---- f32x2 helpers ---------------------------------------------------------
__device__ __forceinline__ ull fma2(ull a, ull b, ull c) {
    ull d;
    asm("fma.rn.f32x2 %0, %1, %2, %3;" : "=l"(d) : "l"(a), "l"(b), "l"(c));
    return d;
}
union F2U { ull u; float2 f; };
__device__ __forceinline__ ull pack2(float lo, float hi) {
    F2U t; t.f = make_float2(lo, hi); return t.u;
}
__device__ __forceinline__ void mina(float2& m, ull v) {
    F2U t; t.u = v;
    m.x = fminf(m.x, t.f.x);
    m.y = fminf(m.y, t.f.y);
}

// ---------------------------------------------------------------------------
// Kernel 1 (fused): grid = 128 + KCH blocks, 256 threads.
//   blocks [0,128):  (tile, quarter) min blocks. Each block deterministically
//                    compacts its batch's probes into shared (pair-SoA with
//                    sentinel pads), then min-reduces its probe quarter over
//                    1024 nodes (G=4 register blocking, f32x2 packed math).
//   blocks [128, ..): K-split partial folded coefficients.
// ---------------------------------------------------------------------------
__global__ __launch_bounds__(256) void main1_kernel(
    const float*    __restrict__ locs,
    const unsigned* __restrict__ probe_raw,
    const float*    __restrict__ W_node,
    const float*    __restrict__ b_node,
    const float*    __restrict__ W_dist,
    const float*    __restrict__ b_dist,
    const float*    __restrict__ W_out)
{
    int blk = blockIdx.x;
    int tid = threadIdx.x;

    if (blk >= 128) {
        // ---- folded coefficients, K-chunk c ----
        int c = blk - 128;
        int e = tid;
        float a0 = 0.f, a1 = 0.f, cc = 0.f, dd = 0.f;
        int k0 = c * (EE / KCH);
        #pragma unroll 8
        for (int kk = 0; kk < EE / KCH; kk++) {
            int k = k0 + kk;
            float wt = W_out[k * EE + e];
            float wb = W_out[(EE + k) * EE + e];
            a0 = fmaf(W_node[k],      wt, a0);
            a1 = fmaf(W_node[EE + k], wt, a1);
            cc = fmaf(W_dist[k],      wb, cc);
            dd = fmaf(b_node[k], wt, dd);
            dd = fmaf(b_dist[k], wb, dd);
        }
        g_part[c][0][e] = a0;
        g_part[c][1][e] = a1;
        g_part[c][2][e] = cc;
        g_part[c][3][e] = dd;
        return;
    }

    // ---- min block: (tile, quarter) ----
    int tile  = blk >> 2;               // 0..31 (1024-node tiles)
    int s     = blk & 3;                // probe quarter
    int b     = tile >> 1;              // batch
    int nbase = (tile & 1) << 10;

    __shared__ float4 s_xy4[NN / 2];    // pair-SoA (x0,x1,y0,y1), 16KB
    __shared__ ull    s_zz [NN / 2];    // pair (z0,z1), 8KB
    __shared__ int    s_wc[8];          // per-warp compaction counts

    // dtype detect on 512 words (valid reads under both candidate layouts)
    bool bad = false;
    #pragma unroll
    for (int j = 0; j < 2; j++) {
        unsigned v = probe_raw[b * 512 + j * 256 + tid];
        if (v != 0u && v != 1u && v != 0x3F800000u) bad = true;
    }
    int is8 = __syncthreads_or((int)bad);

    // load this batch's flags + probe coords (strided, 8 elems/thread)
    const float2* lp = (const float2*)locs + b * NN;
    unsigned hit[8];
    float2   pl[8];
    if (is8) {
        const unsigned char* p8 = (const unsigned char*)probe_raw + b * NN;
        #pragma unroll
        for (int j = 0; j < 8; j++) hit[j] = p8[tid + j * 256];
    } else {
        const unsigned* p32 = probe_raw + b * NN;
        #pragma unroll
        for (int j = 0; j < 8; j++) hit[j] = p32[tid + j * 256];
    }
    #pragma unroll
    for (int j = 0; j < 8; j++) pl[j] = lp[tid + j * 256];

    // deterministic block-wide compaction into shared pair-SoA
    float*   sxyf = (float*)s_xy4;
    float*   szf  = (float*)s_zz;
    int wid = tid >> 5, lid = tid & 31;
    unsigned lmask = (1u << lid) - 1u;
    int base = 0;
    #pragma unroll
    for (int j = 0; j < 8; j++) {
        bool h = hit[j] != 0u;
        unsigned bal = __ballot_sync(0xFFFFFFFFu, h);
        if (lid == 0) s_wc[wid] = __popc(bal);
        __syncthreads();
        int pre = base, total = 0;
        #pragma unroll
        for (int w = 0; w < 8; w++) {
            int c = s_wc[w];
            if (w < wid) pre += c;
            total += c;
        }
        if (h) {
            int q  = pre + __popc(bal & lmask);
            int pr = q >> 1, c = q & 1;
            sxyf[pr * 4 + c]     = pl[j].x;
            sxyf[pr * 4 + 2 + c] = pl[j].y;
            szf [pr * 2 + c]     = fmaf(pl[j].x, pl[j].x, pl[j].y * pl[j].y);
        }
        base += total;
        __syncthreads();
    }
    int P    = base;
    int Ppad = (P + 63) & ~63;          // probes, multiple of 64
    for (int q = P + tid; q < Ppad; q += 256) {
        int pr = q >> 1, c = q & 1;
        sxyf[pr * 4 + c]     = 0.f;
        sxyf[pr * 4 + 2 + c] = 0.f;
        szf [pr * 2 + c]     = 3.2e38f;
    }

    // node coords + packed query terms (G=4 nodes per thread)
    float2 me[4];
    ull tx2[4], ty2[4];
    float2 m[4];
    #pragma unroll
    for (int g = 0; g < 4; g++) {
        me[g] = lp[nbase + tid + (g << 8)];
        float ntx = -2.f * me[g].x, nty = -2.f * me[g].y;
        tx2[g] = pack2(ntx, ntx);
        ty2[g] = pack2(nty, nty);
        m[g]   = make_float2(3.4e38f, 3.4e38f);
    }
    __syncthreads();

    // min loop over this block's probe quarter
    int npq  = Ppad >> 3;               // pairs per quarter (multiple of 8)
    int i0   = s * npq;
    int iend = i0 + npq;
    const ulonglong2* sxy = (const ulonglong2*)s_xy4;
    for (int i = i0; i < iend; i += 4) {
        ulonglong2 a0 = sxy[i],     a1 = sxy[i + 1];
        ulonglong2 a2 = sxy[i + 2], a3 = sxy[i + 3];
        ull z0 = s_zz[i], z1 = s_zz[i + 1], z2 = s_zz[i + 2], z3 = s_zz[i + 3];
        #pragma unroll
        for (int g = 0; g < 4; g++) {
            mina(m[g], fma2(ty2[g], a0.y, fma2(tx2[g], a0.x, z0)));
            mina(m[g], fma2(ty2[g], a1.y, fma2(tx2[g], a1.x, z1)));
            mina(m[g], fma2(ty2[g], a2.y, fma2(tx2[g], a2.x, z2)));
            mina(m[g], fma2(ty2[g], a3.y, fma2(tx2[g], a3.x, z3)));
        }
    }
    #pragma unroll
    for (int g = 0; g < 4; g++)
        g_minpart[s][b * NN + nbase + tid + (g << 8)] = fminf(m[g].x, m[g].y);
}

// ---------------------------------------------------------------------------
// Kernel 2: coef reduce + final min + sqrt + affine tile write.
// grid = BB*8 = 128 blocks of 256 threads; block = (batch, 256-node tile).
// ---------------------------------------------------------------------------
__global__ __launch_bounds__(256) void epi_kernel(
    const float* __restrict__ locs,
    const float* __restrict__ b_out,
    float*       __restrict__ out)
{
    __shared__ float4 s_row[256];
    __shared__ float  s_coef[4][EE];

    int b     = blockIdx.x >> 3;
    int nbase = (blockIdx.x & 7) << 8;
    int tid   = threadIdx.x;

    {   // folded coefficients, fixed-order reduce
        float c0 = 0.f, c1 = 0.f, c2 = 0.f, c3 = 0.f;
        #pragma unroll
        for (int c = 0; c < KCH; c++) {
            c0 += g_part[c][0][tid];
            c1 += g_part[c][1][tid];
            c2 += g_part[c][2][tid];
            c3 += g_part[c][3][tid];
        }
        s_coef[0][tid] = c0;
        s_coef[1][tid] = c1;
        s_coef[2][tid] = c2;
        s_coef[3][tid] = c3 + b_out[tid];
    }

    int node  = b * NN + nbase + tid;
    float2 me = ((const float2*)locs)[node];
    float p0 = g_minpart[0][node], p1 = g_minpart[1][node];
    float p2 = g_minpart[2][node], p3 = g_minpart[3][node];
    float ms = fminf(fminf(p0, p1), fminf(p2, p3));
    float d2 = fmaxf(fmaf(me.x, me.x, me.y * me.y) + ms, 0.f);
    s_row[tid] = make_float4(me.x, me.y, sqrtf(d2), 0.f);
    __syncthreads();

    int e0   = (tid & 63) << 2;
    int rsub = tid >> 6;
    float4 A0 = *(const float4*)&s_coef[0][e0];
    float4 A1 = *(const float4*)&s_coef[1][e0];
    float4 C  = *(const float4*)&s_coef[2][e0];
    float4 Dv = *(const float4*)&s_coef[3][e0];

    int rowbase = b * NN + nbase;
    #pragma unroll 4
    for (int r0 = 0; r0 < 256; r0 += 4) {
        int r = r0 + rsub;
        float4 rw = s_row[r];
        float4 v;
        v.x = fmaf(rw.x, A0.x, fmaf(rw.y, A1.x, fmaf(rw.z, C.x, Dv.x)));
        v.y = fmaf(rw.x, A0.y, fmaf(rw.y, A1.y, fmaf(rw.z, C.y, Dv.y)));
        v.z = fmaf(rw.x, A0.z, fmaf(rw.y, A1.z, fmaf(rw.z, C.z, Dv.z)));
        v.w = fmaf(rw.x, A0.w, fmaf(rw.y, A1.w, fmaf(rw.z, C.w, Dv.w)));
        *(float4*)(out + (size_t)(rowbase + r) * EE + e0) = v;
    }
}

// ---------------------------------------------------------------------------
extern "C" void kernel_launch(void* const* d_in, const int* in_sizes, int n_in,
                              void* d_out, int out_size)
{
    const float*    locs   = (const float*)d_in[0];
    const unsigned* probe  = (const unsigned*)d_in[1];
    const float*    W_node = (const float*)d_in[2];
    const float*    b_node = (const float*)d_in[3];
    const float*    W_dist = (const float*)d_in[4];
    const float*    b_dist = (const float*)d_in[5];
    const float*    W_out  = (const float*)d_in[6];
    const float*    b_out  = (const float*)d_in[7];
    float* out = (float*)d_out;

    main1_kernel<<<128 + KCH, 256>>>(locs, probe, W_node, b_node, W_dist, b_dist, W_out);
    epi_kernel<<<128, 256>>>(locs, b_out, out);
}